// round 1
// baseline (speedup 1.0000x reference)
#include <cuda_runtime.h>
#include <math_constants.h>

#define NB      64          // batches
#define HW      262144      // 512*512 per batch
#define WIDTH   512
#define CHUNKS  16
#define TPB     256
#define ELEMS_PER_CHUNK (HW / CHUNKS)          // 16384
#define VEC4_PER_CHUNK  (ELEMS_PER_CHUNK / 4)  // 4096
#define ITERS   (VEC4_PER_CHUNK / TPB)         // 16

// Scratch (device globals — no allocation allowed in kernel_launch)
__device__ float g_pmax[NB * CHUNKS];
__device__ int   g_pidx[NB * CHUNKS];
__device__ float g_lmax[NB * CHUNKS];
__device__ int   g_lidx[NB * CHUNKS];
__device__ float g_sq  [NB * CHUNKS];

__global__ void __launch_bounds__(TPB) loss_pass1(
    const float* __restrict__ pred, const float* __restrict__ label)
{
    const int b = blockIdx.y;
    const int c = blockIdx.x;
    const int t = threadIdx.x;

    const float4* __restrict__ p4 = (const float4*)(pred  + (size_t)b * HW);
    const float4* __restrict__ l4 = (const float4*)(label + (size_t)b * HW);
    const int base4 = c * VEC4_PER_CHUNK;

    float pm = -CUDART_INF_F; int pi = 0;
    float lm = -CUDART_INF_F; int li = 0;
    float ss = 0.0f;

    #pragma unroll
    for (int it = 0; it < ITERS; ++it) {
        const int i4  = base4 + it * TPB + t;
        const float4 p = p4[i4];
        const float4 l = l4[i4];
        const int idx = i4 * 4;

        float pv[4] = {p.x, p.y, p.z, p.w};
        float lv[4] = {l.x, l.y, l.z, l.w};
        #pragma unroll
        for (int j = 0; j < 4; ++j) {
            float d = pv[j] - lv[j];
            ss = fmaf(d, d, ss);
            // strict > keeps first occurrence within this thread's
            // monotonically increasing index stream
            if (pv[j] > pm) { pm = pv[j]; pi = idx + j; }
            if (lv[j] > lm) { lm = lv[j]; li = idx + j; }
        }
    }

    __shared__ float spm[TPB]; __shared__ int spi[TPB];
    __shared__ float slm[TPB]; __shared__ int sli[TPB];
    __shared__ float sss[TPB];
    spm[t] = pm; spi[t] = pi;
    slm[t] = lm; sli[t] = li;
    sss[t] = ss;
    __syncthreads();

    #pragma unroll
    for (int s = TPB / 2; s > 0; s >>= 1) {
        if (t < s) {
            // tie-break to smaller index => global first-occurrence argmax
            if (spm[t+s] > spm[t] || (spm[t+s] == spm[t] && spi[t+s] < spi[t])) {
                spm[t] = spm[t+s]; spi[t] = spi[t+s];
            }
            if (slm[t+s] > slm[t] || (slm[t+s] == slm[t] && sli[t+s] < sli[t])) {
                slm[t] = slm[t+s]; sli[t] = sli[t+s];
            }
            sss[t] += sss[t+s];
        }
        __syncthreads();
    }

    if (t == 0) {
        const int o = b * CHUNKS + c;
        g_pmax[o] = spm[0]; g_pidx[o] = spi[0];
        g_lmax[o] = slm[0]; g_lidx[o] = sli[0];
        g_sq[o]   = sss[0];
    }
}

__global__ void loss_pass2(float* __restrict__ out)
{
    const int t = threadIdx.x;  // 64 threads, one per batch

    float  pm = -CUDART_INF_F; int pi = 0;
    float  lm = -CUDART_INF_F; int li = 0;
    double ss = 0.0;

    #pragma unroll
    for (int c = 0; c < CHUNKS; ++c) {
        const int o = t * CHUNKS + c;
        float v; int ix;
        v = g_pmax[o]; ix = g_pidx[o];
        if (v > pm || (v == pm && ix < pi)) { pm = v; pi = ix; }
        v = g_lmax[o]; ix = g_lidx[o];
        if (v > lm || (v == lm && ix < li)) { lm = v; li = ix; }
        ss += (double)g_sq[o];
    }

    const float rp = (float)(pi / WIDTH), cp = (float)(pi % WIDTH);
    const float rl = (float)(li / WIDTH), cl = (float)(li % WIDTH);
    const float dr = rp - rl, dc = cp - cl;
    const float idxl = dr * dr + dc * dc;

    __shared__ float  sidx[64];
    __shared__ double smse[64];
    sidx[t] = idxl;
    smse[t] = ss;
    __syncthreads();

    #pragma unroll
    for (int s = 32; s > 0; s >>= 1) {
        if (t < s) { sidx[t] += sidx[t+s]; smse[t] += smse[t+s]; }
        __syncthreads();
    }

    if (t == 0) {
        const float I = sidx[0];
        const float M = (float)smse[0];
        const float alpha = (I != 0.0f) ? (M / I) : 1.0f;
        out[0] = (M + 0.25f * alpha * I) / (float)NB;
    }
}

extern "C" void kernel_launch(void* const* d_in, const int* in_sizes, int n_in,
                              void* d_out, int out_size)
{
    const float* pred  = (const float*)d_in[0];
    const float* label = (const float*)d_in[1];
    float* out = (float*)d_out;

    dim3 grid(CHUNKS, NB);
    loss_pass1<<<grid, TPB>>>(pred, label);
    loss_pass2<<<1, 64>>>(out);
}

// round 2
// speedup vs baseline: 1.0702x; 1.0702x over previous
#include <cuda_runtime.h>
#include <math_constants.h>

#define NB      64          // batches
#define HW      262144      // 512*512 per batch
#define WIDTH   512
#define CHUNKS  16
#define TPB     256
#define NBLOCKS (NB * CHUNKS)                  // 1024
#define ELEMS_PER_CHUNK (HW / CHUNKS)          // 16384
#define VEC4_PER_CHUNK  (ELEMS_PER_CHUNK / 4)  // 4096
#define ITERS   (VEC4_PER_CHUNK / TPB)         // 16
#define UF      4                              // load batch (MLP)
#define GROUPS  (ITERS / UF)                   // 4

// Scratch (device globals — no allocation allowed)
__device__ float g_pmax[NBLOCKS];
__device__ int   g_pidx[NBLOCKS];
__device__ float g_lmax[NBLOCKS];
__device__ int   g_lidx[NBLOCKS];
__device__ float g_sq  [NBLOCKS];
__device__ unsigned int g_count = 0;

__device__ __forceinline__ void amax_upd(float v, int ix, float& m, int& mi) {
    if (v > m || (v == m && ix < mi)) { m = v; mi = ix; }
}

__global__ void __launch_bounds__(TPB) loss_fused(
    const float* __restrict__ pred, const float* __restrict__ label,
    float* __restrict__ out)
{
    const int b = blockIdx.y;
    const int c = blockIdx.x;
    const int t = threadIdx.x;

    const float4* __restrict__ p4 = (const float4*)(pred  + (size_t)b * HW);
    const float4* __restrict__ l4 = (const float4*)(label + (size_t)b * HW);
    const int base4 = c * VEC4_PER_CHUNK;

    float pm = -CUDART_INF_F; int pi = 0;
    float lm = -CUDART_INF_F; int li = 0;
    float ss = 0.0f;

    #pragma unroll
    for (int g = 0; g < GROUPS; ++g) {
        float4 P[UF], L[UF];
        // batch all loads first -> 8 outstanding LDG.128
        #pragma unroll
        for (int u = 0; u < UF; ++u) {
            const int i4 = base4 + (g * UF + u) * TPB + t;
            P[u] = p4[i4];
            L[u] = l4[i4];
        }
        #pragma unroll
        for (int u = 0; u < UF; ++u) {
            const int idx = (base4 + (g * UF + u) * TPB + t) * 4;
            float pv[4] = {P[u].x, P[u].y, P[u].z, P[u].w};
            float lv[4] = {L[u].x, L[u].y, L[u].z, L[u].w};
            #pragma unroll
            for (int j = 0; j < 4; ++j) {
                float d = pv[j] - lv[j];
                ss = fmaf(d, d, ss);
                if (pv[j] > pm) { pm = pv[j]; pi = idx + j; }
                if (lv[j] > lm) { lm = lv[j]; li = idx + j; }
            }
        }
    }

    __shared__ float spm[TPB]; __shared__ int spi[TPB];
    __shared__ float slm[TPB]; __shared__ int sli[TPB];
    __shared__ float sss[TPB];
    spm[t] = pm; spi[t] = pi;
    slm[t] = lm; sli[t] = li;
    sss[t] = ss;
    __syncthreads();

    #pragma unroll
    for (int s = TPB / 2; s > 0; s >>= 1) {
        if (t < s) {
            if (spm[t+s] > spm[t] || (spm[t+s] == spm[t] && spi[t+s] < spi[t])) {
                spm[t] = spm[t+s]; spi[t] = spi[t+s];
            }
            if (slm[t+s] > slm[t] || (slm[t+s] == slm[t] && sli[t+s] < sli[t])) {
                slm[t] = slm[t+s]; sli[t] = sli[t+s];
            }
            sss[t] += sss[t+s];
        }
        __syncthreads();
    }

    __shared__ bool is_last;
    if (t == 0) {
        const int o = b * CHUNKS + c;
        g_pmax[o] = spm[0]; g_pidx[o] = spi[0];
        g_lmax[o] = slm[0]; g_lidx[o] = sli[0];
        g_sq[o]   = sss[0];
        __threadfence();
        unsigned int n = atomicAdd(&g_count, 1u);
        is_last = (n == NBLOCKS - 1);
    }
    __syncthreads();
    if (!is_last) return;

    // ---- final reduction, partials are L2-hot ----
    // 4 threads per batch, each folds 4 chunk-partials (all loads parallel)
    {
        const int fb = t >> 2;        // batch 0..63
        const int cg = t & 3;         // chunk group 0..3

        float fpm = -CUDART_INF_F; int fpi = 0;
        float flm = -CUDART_INF_F; int fli = 0;
        float fss = 0.0f;

        #pragma unroll
        for (int k = 0; k < 4; ++k) {
            const int o = fb * CHUNKS + cg * 4 + k;
            amax_upd(g_pmax[o], g_pidx[o], fpm, fpi);
            amax_upd(g_lmax[o], g_lidx[o], flm, fli);
            fss += g_sq[o];
        }

        // fold the 4 lanes of each batch (lanes 4b..4b+3 are warp-contiguous)
        #pragma unroll
        for (int off = 2; off > 0; off >>= 1) {
            float v  = __shfl_down_sync(0xffffffffu, fpm, off, 4);
            int   ix = __shfl_down_sync(0xffffffffu, fpi, off, 4);
            amax_upd(v, ix, fpm, fpi);
            v  = __shfl_down_sync(0xffffffffu, flm, off, 4);
            ix = __shfl_down_sync(0xffffffffu, fli, off, 4);
            amax_upd(v, ix, flm, fli);
            fss += __shfl_down_sync(0xffffffffu, fss, off, 4);
        }

        __shared__ float sidx[64];
        __shared__ float smse[64];
        if (cg == 0) {
            const float rp = (float)(fpi / WIDTH), cp = (float)(fpi % WIDTH);
            const float rl = (float)(fli / WIDTH), cl = (float)(fli % WIDTH);
            const float dr = rp - rl, dc = cp - cl;
            sidx[fb] = dr * dr + dc * dc;
            smse[fb] = fss;
        }
        __syncthreads();

        if (t < 32) {
            float I = sidx[t] + sidx[t + 32];
            float M = smse[t] + smse[t + 32];
            #pragma unroll
            for (int off = 16; off > 0; off >>= 1) {
                I += __shfl_down_sync(0xffffffffu, I, off);
                M += __shfl_down_sync(0xffffffffu, M, off);
            }
            if (t == 0) {
                const float alpha = (I != 0.0f) ? (M / I) : 1.0f;
                out[0] = (M + 0.25f * alpha * I) / (float)NB;
                g_count = 0;  // reset for next graph replay (deterministic)
            }
        }
    }
}

extern "C" void kernel_launch(void* const* d_in, const int* in_sizes, int n_in,
                              void* d_out, int out_size)
{
    const float* pred  = (const float*)d_in[0];
    const float* label = (const float*)d_in[1];
    float* out = (float*)d_out;

    dim3 grid(CHUNKS, NB);
    loss_fused<<<grid, TPB>>>(pred, label, out);
}